// round 16
// baseline (speedup 1.0000x reference)
#include <cuda_runtime.h>
#include <cuda_fp16.h>
#include <cstdint>

#define NB 32
#define S  512
#define NC 16            // K chunks of 32 (K=512)
#define NT 512           // threads per GEMM block
#define STAGE0  40960    // mode0 stage bytes (4 tiles x 10240), 2 stages
#define STAGE12 18944    // modes 1/2 stage bytes, 4 stages
#define PGRID 148
#define PKN_B 272        // kn tile pitch bytes (32 rows x 256B data)
#define PMK_B 80         // mk tile pitch bytes (128 rows x 64B data)

// ---------------------------------------------------------------------------
// Device-global scratch
// ---------------------------------------------------------------------------
__device__ __align__(16) float g_E[(size_t)NB * S * S];
__device__ float g_cmax[NB * S], g_cinv[NB * S];
__device__ unsigned int g_ctr0, g_ctr12;

#define HARR(name) __device__ __align__(16) __half name[(size_t)NB * S * S]
HARR(g_a_hi); HARR(g_a_lo);   // a split fp16; a_hi also = gemm2 B operand
HARR(g_b_hi); HARR(g_b_lo);   // b split fp16; b_hi also = gemm1 B operand
HARR(g_pa);                   // row-softmax(E) fp16
HARR(g_pb);                   // col-softmax(E) fp16

// ---------------------------------------------------------------------------
// cp.async helpers
// ---------------------------------------------------------------------------
__device__ __forceinline__ void cp16(uint32_t dst, const void* src) {
    asm volatile("cp.async.cg.shared.global [%0], [%1], 16;" :: "r"(dst), "l"(src));
}
#define CP_COMMIT() asm volatile("cp.async.commit_group;" ::: "memory")
#define CP_WAIT(n)  asm volatile("cp.async.wait_group %0;" :: "n"(n) : "memory")

__device__ __forceinline__ void cp_mk(const __half* __restrict__ src, uint32_t du, int t) {
    int row = t >> 2, c = t & 3;
    cp16(du + row * PMK_B + c * 16, src + (size_t)row * S + c * 8);
}
__device__ __forceinline__ void cp_kn(const __half* __restrict__ src, uint32_t du, int t) {
    int row = t >> 4, c = t & 15;
    cp16(du + row * PKN_B + c * 16, src + (size_t)row * S + c * 8);
}

// ---------------------------------------------------------------------------
// fp16 split helpers
// ---------------------------------------------------------------------------
__device__ __forceinline__ void split2(float x, unsigned short& h, unsigned short& l) {
    __half hb = __float2half_rn(x);
    __half lb = __float2half_rn(x - __half2float(hb));
    h = __half_as_ushort(hb); l = __half_as_ushort(lb);
}
__device__ __forceinline__ void split4(float4 v, ushort4& h4, ushort4& l4) {
    split2(v.x, h4.x, l4.x); split2(v.y, h4.y, l4.y);
    split2(v.z, h4.z, l4.z); split2(v.w, h4.w, l4.w);
}

// ---------------------------------------------------------------------------
// K0: split a,b -> fp16 hi/lo; reset task counters
// ---------------------------------------------------------------------------
__global__ __launch_bounds__(256)
void k_split(const float* __restrict__ a, const float* __restrict__ bm) {
    if (blockIdx.x == 0 && blockIdx.y == 0 && threadIdx.x == 0) {
        g_ctr0 = 0; g_ctr12 = 0;
    }
    const float* src = blockIdx.y ? bm : a;
    __half* hi = blockIdx.y ? g_b_hi : g_a_hi;
    __half* lo = blockIdx.y ? g_b_lo : g_a_lo;
    size_t i4 = (size_t)blockIdx.x * 256 + threadIdx.x;
    float4 v = ((const float4*)src)[i4];
    ushort4 h4, l4; split4(v, h4, l4);
    ((ushort4*)hi)[i4] = h4;
    ((ushort4*)lo)[i4] = l4;
}

// ---------------------------------------------------------------------------
// K_cstats: column softmax stats, two-pass (max, then sum of exps).
// ---------------------------------------------------------------------------
__global__ __launch_bounds__(512)
void k_cstats() {
    int b  = blockIdx.y;
    int j0 = blockIdx.x * 64;
    int c  = threadIdx.x & 63;
    int r  = threadIdx.x >> 6;      // 0..7
    const float* e = g_E + (size_t)b * S * S + j0 + c;
    __shared__ float red[8][64];

    float m = -3.402823466e38f;
#pragma unroll 8
    for (int i = r * 64; i < (r + 1) * 64; ++i)
        m = fmaxf(m, e[(size_t)i * S]);
    red[r][c] = m;
    __syncthreads();
    float cmv = fmaxf(fmaxf(fmaxf(red[0][c], red[1][c]), fmaxf(red[2][c], red[3][c])),
                      fmaxf(fmaxf(red[4][c], red[5][c]), fmaxf(red[6][c], red[7][c])));
    __syncthreads();

    float s = 0.0f;
#pragma unroll 8
    for (int i = r * 64; i < (r + 1) * 64; ++i)
        s += __expf(e[(size_t)i * S] - cmv);
    red[r][c] = s;
    __syncthreads();
    if (r == 0) {
        float sv = ((red[0][c] + red[1][c]) + (red[2][c] + red[3][c]))
                 + ((red[4][c] + red[5][c]) + (red[6][c] + red[7][c]));
        g_cmax[b * S + j0 + c] = cmv;
        g_cinv[b * S + j0 + c] = 1.0f / sv;
    }
}

// ---------------------------------------------------------------------------
// K_pmat: ONE pass over E -> PA (row softmax; row stats in-block)
//         and PB (col softmax from cmax/cinv). float4 smem loads, 16B stores.
// ---------------------------------------------------------------------------
__global__ __launch_bounds__(256)
void k_pmat() {
    __shared__ float cm[S], ci[S];
    int b = blockIdx.y, r0 = blockIdx.x * 8;
    int t = threadIdx.x, lane = t & 31;
    for (int idx = t; idx < S; idx += 256) {
        cm[idx] = g_cmax[b * S + idx];
        ci[idx] = g_cinv[b * S + idx];
    }
    __syncthreads();

    int row = r0 + (t >> 5);
    int jb  = lane * 16;
    size_t base = (size_t)b * S * S + (size_t)row * S + jb;

    float4 v[4];
#pragma unroll
    for (int q = 0; q < 4; ++q) v[q] = *(const float4*)(g_E + base + q * 4);

    float m = -3.402823466e38f;
#pragma unroll
    for (int q = 0; q < 4; ++q)
        m = fmaxf(m, fmaxf(fmaxf(v[q].x, v[q].y), fmaxf(v[q].z, v[q].w)));
#pragma unroll
    for (int o = 16; o; o >>= 1) m = fmaxf(m, __shfl_xor_sync(0xffffffffu, m, o));

    float x[16];
#pragma unroll
    for (int q = 0; q < 4; ++q) {
        x[q * 4 + 0] = __expf(v[q].x - m);
        x[q * 4 + 1] = __expf(v[q].y - m);
        x[q * 4 + 2] = __expf(v[q].z - m);
        x[q * 4 + 3] = __expf(v[q].w - m);
    }
    float s = 0.0f;
#pragma unroll
    for (int k = 0; k < 16; ++k) s += x[k];
#pragma unroll
    for (int o = 16; o; o >>= 1) s += __shfl_xor_sync(0xffffffffu, s, o);
    float rinv = 1.0f / s;

    unsigned short pa16[16], pb16[16];
#pragma unroll
    for (int q = 0; q < 4; ++q) {
        int j = jb + q * 4;
        float4 cm4 = *(const float4*)(cm + j);
        float4 ci4 = *(const float4*)(ci + j);
        pa16[q * 4 + 0] = __half_as_ushort(__float2half_rn(x[q * 4 + 0] * rinv));
        pa16[q * 4 + 1] = __half_as_ushort(__float2half_rn(x[q * 4 + 1] * rinv));
        pa16[q * 4 + 2] = __half_as_ushort(__float2half_rn(x[q * 4 + 2] * rinv));
        pa16[q * 4 + 3] = __half_as_ushort(__float2half_rn(x[q * 4 + 3] * rinv));
        pb16[q * 4 + 0] = __half_as_ushort(__float2half_rn(__expf(v[q].x - cm4.x) * ci4.x));
        pb16[q * 4 + 1] = __half_as_ushort(__float2half_rn(__expf(v[q].y - cm4.y) * ci4.y));
        pb16[q * 4 + 2] = __half_as_ushort(__float2half_rn(__expf(v[q].z - cm4.z) * ci4.z));
        pb16[q * 4 + 3] = __half_as_ushort(__float2half_rn(__expf(v[q].w - cm4.w) * ci4.w));
    }
    *(uint4*)(g_pa + base)     = *(const uint4*)(pa16);
    *(uint4*)(g_pa + base + 8) = *(const uint4*)(pa16 + 8);
    *(uint4*)(g_pb + base)     = *(const uint4*)(pb16);
    *(uint4*)(g_pb + base + 8) = *(const uint4*)(pb16 + 8);
}

// ---------------------------------------------------------------------------
// Raw PTX: ldmatrix + mma.sync (fp16 in, fp32 accum)
// ---------------------------------------------------------------------------
__device__ __forceinline__ void ldm4(uint32_t* r, uint32_t a) {
    asm volatile("ldmatrix.sync.aligned.m8n8.x4.shared.b16 {%0,%1,%2,%3}, [%4];"
                 : "=r"(r[0]), "=r"(r[1]), "=r"(r[2]), "=r"(r[3]) : "r"(a));
}
__device__ __forceinline__ void ldm4t(uint32_t* r, uint32_t a) {
    asm volatile("ldmatrix.sync.aligned.m8n8.x4.trans.shared.b16 {%0,%1,%2,%3}, [%4];"
                 : "=r"(r[0]), "=r"(r[1]), "=r"(r[2]), "=r"(r[3]) : "r"(a));
}
__device__ __forceinline__ void mma16816(float* c, const uint32_t* a, const uint32_t* b) {
    asm volatile("mma.sync.aligned.m16n8k16.row.col.f32.f16.f16.f32 "
                 "{%0,%1,%2,%3}, {%4,%5,%6,%7}, {%8,%9}, {%0,%1,%2,%3};"
                 : "+f"(c[0]), "+f"(c[1]), "+f"(c[2]), "+f"(c[3])
                 : "r"(a[0]), "r"(a[1]), "r"(a[2]), "r"(a[3]), "r"(b[0]), "r"(b[1]));
}

// ---------------------------------------------------------------------------
// compute one 32-k chunk.
// MODE 0: 3-term split, liveness-minimized ordering (hh -> lh -> hl).
// MODES 1/2: single term.
// ---------------------------------------------------------------------------
template <int MODE>
__device__ __forceinline__ void compute_chunk(uint32_t sb, float acc[2][4][4],
                                              int wm, int wn, int lane) {
    if (MODE == 0) {
        const uint32_t A_hi = sb, A_lo = sb + 10240;
        const uint32_t B_hi = sb + 20480, B_lo = sb + 30720;
#pragma unroll
        for (int ks = 0; ks < 2; ++ks) {
            uint32_t ah[2][4], a2[2][4], bf[4][2];
            uint32_t aoff[2], boff[2];
#pragma unroll
            for (int mi = 0; mi < 2; ++mi)
                aoff[mi] = (uint32_t)((wm * 32 + mi * 16 + (lane & 15)) * PMK_B
                                      + ks * 32 + ((lane >> 4) << 4));
#pragma unroll
            for (int nb = 0; nb < 2; ++nb)
                boff[nb] = (uint32_t)((wn * 32 + nb * 16 + (lane & 7) + ((lane >> 4) << 3)) * PMK_B
                                      + ks * 32 + (((lane >> 3) & 1) << 4));
#pragma unroll
            for (int mi = 0; mi < 2; ++mi) ldm4(ah[mi], A_hi + aoff[mi]);
#pragma unroll
            for (int nb = 0; nb < 2; ++nb) {
                uint32_t r4[4];
                ldm4(r4, B_hi + boff[nb]);
                bf[nb * 2][0] = r4[0]; bf[nb * 2][1] = r4[1];
                bf[nb * 2 + 1][0] = r4[2]; bf[nb * 2 + 1][1] = r4[3];
            }
#pragma unroll
            for (int mi = 0; mi < 2; ++mi)
#pragma unroll
                for (int nf = 0; nf < 4; ++nf) mma16816(acc[mi][nf], ah[mi], bf[nf]);
#pragma unroll
            for (int mi = 0; mi < 2; ++mi) ldm4(a2[mi], A_lo + aoff[mi]);
#pragma unroll
            for (int mi = 0; mi < 2; ++mi)
#pragma unroll
                for (int nf = 0; nf < 4; ++nf) mma16816(acc[mi][nf], a2[mi], bf[nf]);
#pragma unroll
            for (int nb = 0; nb < 2; ++nb) {
                uint32_t r4[4];
                ldm4(r4, B_lo + boff[nb]);
                bf[nb * 2][0] = r4[0]; bf[nb * 2][1] = r4[1];
                bf[nb * 2 + 1][0] = r4[2]; bf[nb * 2 + 1][1] = r4[3];
            }
#pragma unroll
            for (int mi = 0; mi < 2; ++mi)
#pragma unroll
                for (int nf = 0; nf < 4; ++nf) mma16816(acc[mi][nf], ah[mi], bf[nf]);
        }
    } else {
        const uint32_t A0 = sb, B0 = sb + 10240;
#pragma unroll
        for (int ks = 0; ks < 2; ++ks) {
            uint32_t ah[2][4], bh[4][2];
#pragma unroll
            for (int mi = 0; mi < 2; ++mi) {
                if (MODE == 2) {
                    uint32_t ao = (uint32_t)((ks * 16 + (lane & 7) + ((lane >> 4) << 3)) * PKN_B
                                             + (wm * 32 + mi * 16 + (((lane >> 3) & 1) << 3)) * 2);
                    ldm4t(ah[mi], A0 + ao);
                } else {
                    uint32_t ao = (uint32_t)((wm * 32 + mi * 16 + (lane & 15)) * PMK_B
                                             + ks * 32 + ((lane >> 4) << 4));
                    ldm4(ah[mi], A0 + ao);
                }
            }
#pragma unroll
            for (int nb = 0; nb < 2; ++nb) {
                uint32_t bo = (uint32_t)((ks * 16 + (lane & 15)) * PKN_B
                                         + (wn * 32 + nb * 16 + ((lane >> 4) << 3)) * 2);
                uint32_t r4[4];
                ldm4t(r4, B0 + bo);
                bh[nb * 2][0] = r4[0]; bh[nb * 2][1] = r4[1];
                bh[nb * 2 + 1][0] = r4[2]; bh[nb * 2 + 1][1] = r4[3];
            }
#pragma unroll
            for (int mi = 0; mi < 2; ++mi)
#pragma unroll
                for (int nf = 0; nf < 4; ++nf) mma16816(acc[mi][nf], ah[mi], bh[nf]);
        }
    }
}

// ---------------------------------------------------------------------------
// Persistent gemm0 (E = a.b^T), 2 CTAs/SM, 2-stage pipeline,
// next-task prefetch overlapped with the E-store epilogue.
// ---------------------------------------------------------------------------
__global__ __launch_bounds__(NT, 2)
void k_gemm0p(const float* __restrict__ a, const float* __restrict__ bm,
              float* __restrict__ out) {
    extern __shared__ char sm[];
    uint32_t su = (uint32_t)__cvta_generic_to_shared(sm);
    __shared__ unsigned task_s;
    int t = threadIdx.x, wid = t >> 5, lane = t & 31;
    int wm = wid & 3, wn = wid >> 2;

    if (t == 0) task_s = atomicAdd(&g_ctr0, 1u);
    __syncthreads();
    unsigned task = task_s;
    if (task >= 512u) return;

    const __half *Ah, *Al, *Bh, *Bl;
    int bb, m0, n0;
    auto setup = [&](unsigned tk) {
        bb = tk >> 4; m0 = ((tk >> 2) & 3) * 128; n0 = (tk & 3) * 128;
        size_t bo = (size_t)bb * S * S;
        Ah = g_a_hi + bo + (size_t)m0 * S; Al = g_a_lo + bo + (size_t)m0 * S;
        Bh = g_b_hi + bo + (size_t)n0 * S; Bl = g_b_lo + bo + (size_t)n0 * S;
    };
    auto cpstage = [&](int c) {
        uint32_t stu_ = su + (c & 1) * STAGE0;
        cp_mk(Ah + c * 32, stu_, t);
        cp_mk(Al + c * 32, stu_ + 10240, t);
        cp_mk(Bh + c * 32, stu_ + 20480, t);
        cp_mk(Bl + c * 32, stu_ + 30720, t);
        CP_COMMIT();
    };

    setup(task);
    cpstage(0); cpstage(1);

    for (;;) {
        float acc[2][4][4] = {};
#pragma unroll 1
        for (int c = 0; c < NC; ++c) {
            CP_WAIT(1);
            __syncthreads();
            compute_chunk<0>(su + (c & 1) * STAGE0, acc, wm, wn, lane);
            __syncthreads();
            if (c + 2 < NC) cpstage(c + 2); else CP_COMMIT();
        }
        int obb = bb, om0 = m0, on0 = n0;
        if (t == 0) task_s = atomicAdd(&g_ctr0, 1u);
        __syncthreads();
        unsigned next = task_s;
        if (next < 512u) { setup(next); cpstage(0); cpstage(1); }

        // epilogue (overlaps with next task's prologue cp.async)
        int r = lane >> 2, cg = (lane & 3) * 2;
        float* Eb = g_E + (size_t)obb * S * S;
#pragma unroll
        for (int mi = 0; mi < 2; ++mi)
#pragma unroll
            for (int nf = 0; nf < 4; ++nf) {
                int m = om0 + wm * 32 + mi * 16 + r;
                int n = on0 + wn * 32 + nf * 8 + cg;
                *(float2*)(Eb + (size_t)m * S + n)       = make_float2(acc[mi][nf][0], acc[mi][nf][1]);
                *(float2*)(Eb + (size_t)(m + 8) * S + n) = make_float2(acc[mi][nf][2], acc[mi][nf][3]);
            }
        if (next >= 512u) return;
    }
}

// ---------------------------------------------------------------------------
// Persistent gemm12 (m_a / m_b), 2 CTAs/SM, 4-stage pipeline,
// direct register epilogue with streaming stores + next-task prefetch.
// ---------------------------------------------------------------------------
__global__ __launch_bounds__(NT, 2)
void k_gemm12p(const float* __restrict__ a, const float* __restrict__ bm,
               float* __restrict__ out) {
    extern __shared__ char sm[];
    uint32_t su = (uint32_t)__cvta_generic_to_shared(sm);
    __shared__ unsigned task_s;
    int t = threadIdx.x, wid = t >> 5, lane = t & 31;
    int wm = wid & 3, wn = wid >> 2;

    if (t == 0) task_s = atomicAdd(&g_ctr12, 1u);
    __syncthreads();
    unsigned task = task_s;
    if (task >= 1024u) return;

    const __half *Ah, *Bh;
    int bb, m0, n0, mode;
    auto setup = [&](unsigned tk) {
        unsigned sub = tk & 511u;
        bb = sub >> 4; m0 = ((sub >> 2) & 3) * 128; n0 = (sub & 3) * 128;
        mode = (tk < 512u) ? 1 : 2;
        size_t bo = (size_t)bb * S * S;
        if (mode == 1) { Ah = g_pa + bo + (size_t)m0 * S; Bh = g_b_hi + bo + n0; }
        else           { Ah = g_pb + bo + m0;             Bh = g_a_hi + bo + n0; }
    };
    auto cpstage = [&](int c) {
        uint32_t stu_ = su + (c & 3) * STAGE12;
        if (mode == 1) cp_mk(Ah + c * 32, stu_, t);
        else           cp_kn(Ah + (size_t)c * 32 * S, stu_, t);
        cp_kn(Bh + (size_t)c * 32 * S, stu_ + 10240, t);
        CP_COMMIT();
    };

    setup(task);
    cpstage(0); cpstage(1); cpstage(2);

    for (;;) {
        float acc[2][4][4] = {};
        int cmode = mode;
#pragma unroll 1
        for (int c = 0; c < NC; ++c) {
            CP_WAIT(2);
            __syncthreads();
            if (c + 3 < NC) cpstage(c + 3); else CP_COMMIT();
            if (cmode == 1) compute_chunk<1>(su + (c & 3) * STAGE12, acc, wm, wn, lane);
            else            compute_chunk<2>(su + (c & 3) * STAGE12, acc, wm, wn, lane);
        }
        __syncthreads();
        int obb = bb, om0 = m0, on0 = n0, omode = cmode;
        if (t == 0) task_s = atomicAdd(&g_ctr12, 1u);
        __syncthreads();
        unsigned next = task_s;
        if (next < 1024u) { setup(next); cpstage(0); cpstage(1); cpstage(2); }

        // direct register epilogue (overlaps next task's prologue cp.async)
        const float* base = (omode == 1) ? (a + ((size_t)obb * S + om0) * S + on0)
                                         : (bm + ((size_t)obb * S + om0) * S + on0);
        size_t obase = ((size_t)obb * S + om0) * 2048 + on0;
        if (omode == 2) obase += (size_t)NB * S * 2048;
        float* ob = out + obase;
        int r = lane >> 2, cg = (lane & 3) * 2;
#pragma unroll
        for (int mi = 0; mi < 2; ++mi)
#pragma unroll
            for (int nf = 0; nf < 4; ++nf) {
#pragma unroll
                for (int h = 0; h < 2; ++h) {
                    int m = wm * 32 + mi * 16 + r + h * 8;
                    int n = wn * 32 + nf * 8 + cg;
                    float2 bv = *(const float2*)(base + (size_t)m * S + n);
                    float2 tv = make_float2(acc[mi][nf][h * 2], acc[mi][nf][h * 2 + 1]);
                    float* o = ob + (size_t)m * 2048 + n;
                    __stcs((float2*)(o),        bv);
                    __stcs((float2*)(o + 512),  tv);
                    __stcs((float2*)(o + 1024), make_float2(bv.x - tv.x, bv.y - tv.y));
                    __stcs((float2*)(o + 1536), make_float2(bv.x * tv.x, bv.y * tv.y));
                }
            }
        if (next >= 1024u) return;
    }
}

// ---------------------------------------------------------------------------

extern "C" void kernel_launch(void* const* d_in, const int* in_sizes, int n_in,
                              void* d_out, int out_size) {
    const float* a  = (const float*)d_in[0];
    const float* bm = (const float*)d_in[1];
    float* out = (float*)d_out;
    (void)in_sizes; (void)n_in; (void)out_size;

    const int SMEM0  = 2 * STAGE0;    // 81920  (2 CTAs/SM)
    const int SMEM12 = 4 * STAGE12;   // 75776  (2 CTAs/SM)

    static int configured = 0;
    if (!configured) {
        cudaFuncSetAttribute(k_gemm0p,  cudaFuncAttributeMaxDynamicSharedMemorySize, SMEM0);
        cudaFuncSetAttribute(k_gemm12p, cudaFuncAttributeMaxDynamicSharedMemorySize, SMEM12);
        configured = 1;
    }

    k_split<<<dim3(8192, 2), 256>>>(a, bm);
    k_gemm0p<<<2 * PGRID, NT, SMEM0>>>(a, bm, out);
    k_cstats<<<dim3(8, NB), 512>>>();
    k_pmat<<<dim3(S / 8, NB), 256>>>();
    k_gemm12p<<<2 * PGRID, NT, SMEM12>>>(a, bm, out);
}

// round 17
// speedup vs baseline: 1.0513x; 1.0513x over previous
#include <cuda_runtime.h>
#include <cuda_fp16.h>
#include <cstdint>

#define NB 32
#define S  512
#define NC 16            // K chunks of 32 (K=512)
#define NT 512           // threads per GEMM block
#define STAGE0  40960    // mode0 stage bytes (4 tiles x 10240), 2 stages
#define STAGE12 18944    // modes 1/2 stage bytes, 4 stages
#define PGRID 148
#define PKN_B 272        // kn tile pitch bytes (32 rows x 256B data)
#define PMK_B 80         // mk tile pitch bytes (128 rows x 64B data)
#define PFS 136          // f32 epilogue staging pitch (elements)

// ---------------------------------------------------------------------------
// Device-global scratch
// ---------------------------------------------------------------------------
__device__ __align__(16) float g_E[(size_t)NB * S * S];
__device__ float g_cmax[NB * S], g_cinv[NB * S];
__device__ unsigned int g_ctr0, g_ctr12;

#define HARR(name) __device__ __align__(16) __half name[(size_t)NB * S * S]
HARR(g_a_hi); HARR(g_a_lo);   // a split fp16; a_hi also = gemm2 B operand
HARR(g_b_hi); HARR(g_b_lo);   // b split fp16; b_hi also = gemm1 B operand
HARR(g_pa);                   // row-softmax(E) fp16
HARR(g_pb);                   // col-softmax(E) fp16

// ---------------------------------------------------------------------------
// cp.async helpers
// ---------------------------------------------------------------------------
__device__ __forceinline__ void cp16(uint32_t dst, const void* src) {
    asm volatile("cp.async.cg.shared.global [%0], [%1], 16;" :: "r"(dst), "l"(src));
}
#define CP_COMMIT() asm volatile("cp.async.commit_group;" ::: "memory")
#define CP_WAIT(n)  asm volatile("cp.async.wait_group %0;" :: "n"(n) : "memory")

__device__ __forceinline__ void cp_mk(const __half* __restrict__ src, uint32_t du, int t) {
    int row = t >> 2, c = t & 3;
    cp16(du + row * PMK_B + c * 16, src + (size_t)row * S + c * 8);
}
__device__ __forceinline__ void cp_kn(const __half* __restrict__ src, uint32_t du, int t) {
    int row = t >> 4, c = t & 15;
    cp16(du + row * PKN_B + c * 16, src + (size_t)row * S + c * 8);
}

// ---------------------------------------------------------------------------
// fp16 split helpers
// ---------------------------------------------------------------------------
__device__ __forceinline__ void split2(float x, unsigned short& h, unsigned short& l) {
    __half hb = __float2half_rn(x);
    __half lb = __float2half_rn(x - __half2float(hb));
    h = __half_as_ushort(hb); l = __half_as_ushort(lb);
}
__device__ __forceinline__ void split4(float4 v, ushort4& h4, ushort4& l4) {
    split2(v.x, h4.x, l4.x); split2(v.y, h4.y, l4.y);
    split2(v.z, h4.z, l4.z); split2(v.w, h4.w, l4.w);
}

// ---------------------------------------------------------------------------
// K0: split a,b -> fp16 hi/lo; reset task counters
// ---------------------------------------------------------------------------
__global__ __launch_bounds__(256)
void k_split(const float* __restrict__ a, const float* __restrict__ bm) {
    if (blockIdx.x == 0 && blockIdx.y == 0 && threadIdx.x == 0) {
        g_ctr0 = 0; g_ctr12 = 0;
    }
    const float* src = blockIdx.y ? bm : a;
    __half* hi = blockIdx.y ? g_b_hi : g_a_hi;
    __half* lo = blockIdx.y ? g_b_lo : g_a_lo;
    size_t i4 = (size_t)blockIdx.x * 256 + threadIdx.x;
    float4 v = ((const float4*)src)[i4];
    ushort4 h4, l4; split4(v, h4, l4);
    ((ushort4*)hi)[i4] = h4;
    ((ushort4*)lo)[i4] = l4;
}

// ---------------------------------------------------------------------------
// K_cstats: column softmax stats, two-pass (max, then sum of exps).
// ---------------------------------------------------------------------------
__global__ __launch_bounds__(512)
void k_cstats() {
    int b  = blockIdx.y;
    int j0 = blockIdx.x * 64;
    int c  = threadIdx.x & 63;
    int r  = threadIdx.x >> 6;      // 0..7
    const float* e = g_E + (size_t)b * S * S + j0 + c;
    __shared__ float red[8][64];

    float m = -3.402823466e38f;
#pragma unroll 8
    for (int i = r * 64; i < (r + 1) * 64; ++i)
        m = fmaxf(m, e[(size_t)i * S]);
    red[r][c] = m;
    __syncthreads();
    float cmv = fmaxf(fmaxf(fmaxf(red[0][c], red[1][c]), fmaxf(red[2][c], red[3][c])),
                      fmaxf(fmaxf(red[4][c], red[5][c]), fmaxf(red[6][c], red[7][c])));
    __syncthreads();

    float s = 0.0f;
#pragma unroll 8
    for (int i = r * 64; i < (r + 1) * 64; ++i)
        s += __expf(e[(size_t)i * S] - cmv);
    red[r][c] = s;
    __syncthreads();
    if (r == 0) {
        float sv = ((red[0][c] + red[1][c]) + (red[2][c] + red[3][c]))
                 + ((red[4][c] + red[5][c]) + (red[6][c] + red[7][c]));
        g_cmax[b * S + j0 + c] = cmv;
        g_cinv[b * S + j0 + c] = 1.0f / sv;
    }
}

// ---------------------------------------------------------------------------
// K_pmat: ONE pass over E -> PA (row softmax; row stats in-block)
//         and PB (col softmax from cmax/cinv). float4 smem loads, 16B stores.
// ---------------------------------------------------------------------------
__global__ __launch_bounds__(256)
void k_pmat() {
    __shared__ float cm[S], ci[S];
    int b = blockIdx.y, r0 = blockIdx.x * 8;
    int t = threadIdx.x, lane = t & 31;
    for (int idx = t; idx < S; idx += 256) {
        cm[idx] = g_cmax[b * S + idx];
        ci[idx] = g_cinv[b * S + idx];
    }
    __syncthreads();

    int row = r0 + (t >> 5);
    int jb  = lane * 16;
    size_t base = (size_t)b * S * S + (size_t)row * S + jb;

    float4 v[4];
#pragma unroll
    for (int q = 0; q < 4; ++q) v[q] = *(const float4*)(g_E + base + q * 4);

    float m = -3.402823466e38f;
#pragma unroll
    for (int q = 0; q < 4; ++q)
        m = fmaxf(m, fmaxf(fmaxf(v[q].x, v[q].y), fmaxf(v[q].z, v[q].w)));
#pragma unroll
    for (int o = 16; o; o >>= 1) m = fmaxf(m, __shfl_xor_sync(0xffffffffu, m, o));

    float x[16];
#pragma unroll
    for (int q = 0; q < 4; ++q) {
        x[q * 4 + 0] = __expf(v[q].x - m);
        x[q * 4 + 1] = __expf(v[q].y - m);
        x[q * 4 + 2] = __expf(v[q].z - m);
        x[q * 4 + 3] = __expf(v[q].w - m);
    }
    float s = 0.0f;
#pragma unroll
    for (int k = 0; k < 16; ++k) s += x[k];
#pragma unroll
    for (int o = 16; o; o >>= 1) s += __shfl_xor_sync(0xffffffffu, s, o);
    float rinv = 1.0f / s;

    unsigned short pa16[16], pb16[16];
#pragma unroll
    for (int q = 0; q < 4; ++q) {
        int j = jb + q * 4;
        float4 cm4 = *(const float4*)(cm + j);
        float4 ci4 = *(const float4*)(ci + j);
        pa16[q * 4 + 0] = __half_as_ushort(__float2half_rn(x[q * 4 + 0] * rinv));
        pa16[q * 4 + 1] = __half_as_ushort(__float2half_rn(x[q * 4 + 1] * rinv));
        pa16[q * 4 + 2] = __half_as_ushort(__float2half_rn(x[q * 4 + 2] * rinv));
        pa16[q * 4 + 3] = __half_as_ushort(__float2half_rn(x[q * 4 + 3] * rinv));
        pb16[q * 4 + 0] = __half_as_ushort(__float2half_rn(__expf(v[q].x - cm4.x) * ci4.x));
        pb16[q * 4 + 1] = __half_as_ushort(__float2half_rn(__expf(v[q].y - cm4.y) * ci4.y));
        pb16[q * 4 + 2] = __half_as_ushort(__float2half_rn(__expf(v[q].z - cm4.z) * ci4.z));
        pb16[q * 4 + 3] = __half_as_ushort(__float2half_rn(__expf(v[q].w - cm4.w) * ci4.w));
    }
    *(uint4*)(g_pa + base)     = *(const uint4*)(pa16);
    *(uint4*)(g_pa + base + 8) = *(const uint4*)(pa16 + 8);
    *(uint4*)(g_pb + base)     = *(const uint4*)(pb16);
    *(uint4*)(g_pb + base + 8) = *(const uint4*)(pb16 + 8);
}

// ---------------------------------------------------------------------------
// Raw PTX: ldmatrix + mma.sync (fp16 in, fp32 accum)
// ---------------------------------------------------------------------------
__device__ __forceinline__ void ldm4(uint32_t* r, uint32_t a) {
    asm volatile("ldmatrix.sync.aligned.m8n8.x4.shared.b16 {%0,%1,%2,%3}, [%4];"
                 : "=r"(r[0]), "=r"(r[1]), "=r"(r[2]), "=r"(r[3]) : "r"(a));
}
__device__ __forceinline__ void ldm4t(uint32_t* r, uint32_t a) {
    asm volatile("ldmatrix.sync.aligned.m8n8.x4.trans.shared.b16 {%0,%1,%2,%3}, [%4];"
                 : "=r"(r[0]), "=r"(r[1]), "=r"(r[2]), "=r"(r[3]) : "r"(a));
}
__device__ __forceinline__ void mma16816(float* c, const uint32_t* a, const uint32_t* b) {
    asm volatile("mma.sync.aligned.m16n8k16.row.col.f32.f16.f16.f32 "
                 "{%0,%1,%2,%3}, {%4,%5,%6,%7}, {%8,%9}, {%0,%1,%2,%3};"
                 : "+f"(c[0]), "+f"(c[1]), "+f"(c[2]), "+f"(c[3])
                 : "r"(a[0]), "r"(a[1]), "r"(a[2]), "r"(a[3]), "r"(b[0]), "r"(b[1]));
}

// ---------------------------------------------------------------------------
// compute one 32-k chunk.
// MODE 0: 3-term split, liveness-minimized ordering (hh -> lh -> hl).
// MODES 1/2: single term.
// ---------------------------------------------------------------------------
template <int MODE>
__device__ __forceinline__ void compute_chunk(uint32_t sb, float acc[2][4][4],
                                              int wm, int wn, int lane) {
    if (MODE == 0) {
        const uint32_t A_hi = sb, A_lo = sb + 10240;
        const uint32_t B_hi = sb + 20480, B_lo = sb + 30720;
#pragma unroll
        for (int ks = 0; ks < 2; ++ks) {
            uint32_t ah[2][4], a2[2][4], bf[4][2];
            uint32_t aoff[2], boff[2];
#pragma unroll
            for (int mi = 0; mi < 2; ++mi)
                aoff[mi] = (uint32_t)((wm * 32 + mi * 16 + (lane & 15)) * PMK_B
                                      + ks * 32 + ((lane >> 4) << 4));
#pragma unroll
            for (int nb = 0; nb < 2; ++nb)
                boff[nb] = (uint32_t)((wn * 32 + nb * 16 + (lane & 7) + ((lane >> 4) << 3)) * PMK_B
                                      + ks * 32 + (((lane >> 3) & 1) << 4));
#pragma unroll
            for (int mi = 0; mi < 2; ++mi) ldm4(ah[mi], A_hi + aoff[mi]);
#pragma unroll
            for (int nb = 0; nb < 2; ++nb) {
                uint32_t r4[4];
                ldm4(r4, B_hi + boff[nb]);
                bf[nb * 2][0] = r4[0]; bf[nb * 2][1] = r4[1];
                bf[nb * 2 + 1][0] = r4[2]; bf[nb * 2 + 1][1] = r4[3];
            }
#pragma unroll
            for (int mi = 0; mi < 2; ++mi)
#pragma unroll
                for (int nf = 0; nf < 4; ++nf) mma16816(acc[mi][nf], ah[mi], bf[nf]);
#pragma unroll
            for (int mi = 0; mi < 2; ++mi) ldm4(a2[mi], A_lo + aoff[mi]);
#pragma unroll
            for (int mi = 0; mi < 2; ++mi)
#pragma unroll
                for (int nf = 0; nf < 4; ++nf) mma16816(acc[mi][nf], a2[mi], bf[nf]);
#pragma unroll
            for (int nb = 0; nb < 2; ++nb) {
                uint32_t r4[4];
                ldm4(r4, B_lo + boff[nb]);
                bf[nb * 2][0] = r4[0]; bf[nb * 2][1] = r4[1];
                bf[nb * 2 + 1][0] = r4[2]; bf[nb * 2 + 1][1] = r4[3];
            }
#pragma unroll
            for (int mi = 0; mi < 2; ++mi)
#pragma unroll
                for (int nf = 0; nf < 4; ++nf) mma16816(acc[mi][nf], ah[mi], bf[nf]);
        }
    } else {
        const uint32_t A0 = sb, B0 = sb + 10240;
#pragma unroll
        for (int ks = 0; ks < 2; ++ks) {
            uint32_t ah[2][4], bh[4][2];
#pragma unroll
            for (int mi = 0; mi < 2; ++mi) {
                if (MODE == 2) {
                    uint32_t ao = (uint32_t)((ks * 16 + (lane & 7) + ((lane >> 4) << 3)) * PKN_B
                                             + (wm * 32 + mi * 16 + (((lane >> 3) & 1) << 3)) * 2);
                    ldm4t(ah[mi], A0 + ao);
                } else {
                    uint32_t ao = (uint32_t)((wm * 32 + mi * 16 + (lane & 15)) * PMK_B
                                             + ks * 32 + ((lane >> 4) << 4));
                    ldm4(ah[mi], A0 + ao);
                }
            }
#pragma unroll
            for (int nb = 0; nb < 2; ++nb) {
                uint32_t bo = (uint32_t)((ks * 16 + (lane & 15)) * PKN_B
                                         + (wn * 32 + nb * 16 + ((lane >> 4) << 3)) * 2);
                uint32_t r4[4];
                ldm4t(r4, B0 + bo);
                bh[nb * 2][0] = r4[0]; bh[nb * 2][1] = r4[1];
                bh[nb * 2 + 1][0] = r4[2]; bh[nb * 2 + 1][1] = r4[3];
            }
#pragma unroll
            for (int mi = 0; mi < 2; ++mi)
#pragma unroll
                for (int nf = 0; nf < 4; ++nf) mma16816(acc[mi][nf], ah[mi], bh[nf]);
        }
    }
}

// ---------------------------------------------------------------------------
// One 128x128 tile task. MODE 0: 2-stage pipeline (2 CTAs/SM).
// MODES 1/2: 4-stage pipeline; smem-staged coalesced epilogue with
// streaming (__stcs) float4 output stores.
// ---------------------------------------------------------------------------
template <int MODE>
__device__ __forceinline__ void gemm_tile(const float* __restrict__ a,
                                          const float* __restrict__ bm,
                                          float* __restrict__ out,
                                          int bb, int m0, int n0) {
    constexpr int STG = (MODE == 0) ? STAGE0 : STAGE12;
    extern __shared__ char sm[];
    uint32_t su = (uint32_t)__cvta_generic_to_shared(sm);
    int t = threadIdx.x, wid = t >> 5, lane = t & 31;
    int wm = wid & 3, wn = wid >> 2;
    const size_t bo = (size_t)bb * S * S;

    const __half *Ah, *Al, *Bh, *Bl;
    if (MODE == 0) { Ah = g_a_hi + bo + (size_t)m0 * S; Al = g_a_lo + bo + (size_t)m0 * S;
                     Bh = g_b_hi + bo + (size_t)n0 * S; Bl = g_b_lo + bo + (size_t)n0 * S; }
    if (MODE == 1) { Ah = g_pa + bo + (size_t)m0 * S; Al = nullptr;
                     Bh = g_b_hi + bo + n0;           Bl = nullptr; }
    if (MODE == 2) { Ah = g_pb + bo + m0;             Al = nullptr;
                     Bh = g_a_hi + bo + n0;           Bl = nullptr; }

#define CPSTAGE(c, nst) do {                                                     \
        uint32_t stu_ = su + ((c) % (nst)) * STG;                                \
        if (MODE == 0) { cp_mk(Ah + (c) * 32, stu_, t);                          \
                         cp_mk(Al + (c) * 32, stu_ + 10240, t);                  \
                         cp_mk(Bh + (c) * 32, stu_ + 20480, t);                  \
                         cp_mk(Bl + (c) * 32, stu_ + 30720, t); }                \
        else if (MODE == 1) { cp_mk(Ah + (c) * 32, stu_, t);                     \
                              cp_kn(Bh + (size_t)(c) * 32 * S, stu_ + 10240, t);}\
        else           { cp_kn(Ah + (size_t)(c) * 32 * S, stu_, t);              \
                         cp_kn(Bh + (size_t)(c) * 32 * S, stu_ + 10240, t); }    \
        CP_COMMIT(); } while (0)

    float acc[2][4][4] = {};

    if (MODE == 0) {
        CPSTAGE(0, 2); CPSTAGE(1, 2);
#pragma unroll 1
        for (int c = 0; c < NC; ++c) {
            CP_WAIT(1);
            __syncthreads();
            compute_chunk<0>(su + (c & 1) * STG, acc, wm, wn, lane);
            __syncthreads();
            if (c + 2 < NC) CPSTAGE(c + 2, 2); else CP_COMMIT();
        }
    } else {
        CPSTAGE(0, 4); CPSTAGE(1, 4); CPSTAGE(2, 4);
#pragma unroll 1
        for (int c = 0; c < NC; ++c) {
            CP_WAIT(2);
            __syncthreads();
            if (c + 3 < NC) CPSTAGE(c + 3, 4); else CP_COMMIT();
            compute_chunk<MODE>(su + (c & 3) * STG, acc, wm, wn, lane);
        }
        __syncthreads();
    }

    int r  = lane >> 2;
    int cg = (lane & 3) * 2;

    if (MODE == 0) {
        float* Eb = g_E + bo;
#pragma unroll
        for (int mi = 0; mi < 2; ++mi)
#pragma unroll
            for (int nf = 0; nf < 4; ++nf) {
                int m = m0 + wm * 32 + mi * 16 + r;
                int n = n0 + wn * 32 + nf * 8 + cg;
                *(float2*)(Eb + (size_t)m * S + n)       = make_float2(acc[mi][nf][0], acc[mi][nf][1]);
                *(float2*)(Eb + (size_t)(m + 8) * S + n) = make_float2(acc[mi][nf][2], acc[mi][nf][3]);
            }
        return;
    }

    float* fs = (float*)sm;
#pragma unroll
    for (int mi = 0; mi < 2; ++mi)
#pragma unroll
        for (int nf = 0; nf < 4; ++nf) {
            int m = wm * 32 + mi * 16 + r;
            int n = wn * 32 + nf * 8 + cg;
            *(float2*)(fs + (size_t)m * PFS + n)       = make_float2(acc[mi][nf][0], acc[mi][nf][1]);
            *(float2*)(fs + (size_t)(m + 8) * PFS + n) = make_float2(acc[mi][nf][2], acc[mi][nf][3]);
        }
    __syncthreads();

    const float* base = (MODE == 1) ? (a + ((size_t)bb * S + m0) * S + n0)
                                    : (bm + ((size_t)bb * S + m0) * S + n0);
    size_t obase = ((size_t)bb * S + m0) * 2048 + n0;
    if (MODE == 2) obase += (size_t)NB * S * 2048;
    float* ob = out + obase;
#pragma unroll
    for (int p = 0; p < 8; ++p) {
        int idx = t + p * NT;
        int rr = idx >> 5, d4 = idx & 31;
        float4 xv = *(const float4*)(base + (size_t)rr * S + 4 * d4);
        float4 tv = *(const float4*)(fs + (size_t)rr * PFS + 4 * d4);
        float* o = ob + (size_t)rr * 2048 + 4 * d4;
        __stcs((float4*)(o),        xv);
        __stcs((float4*)(o + 512),  tv);
        __stcs((float4*)(o + 1024), make_float4(xv.x - tv.x, xv.y - tv.y, xv.z - tv.z, xv.w - tv.w));
        __stcs((float4*)(o + 1536), make_float4(xv.x * tv.x, xv.y * tv.y, xv.z * tv.z, xv.w * tv.w));
    }
#undef CPSTAGE
}

// ---------------------------------------------------------------------------
// Persistent GEMM kernels with dynamic tile scheduling (2 CTAs/SM)
// ---------------------------------------------------------------------------
__global__ __launch_bounds__(NT, 2)
void k_gemm0p(const float* __restrict__ a, const float* __restrict__ bm,
              float* __restrict__ out) {
    __shared__ unsigned task_s;
    for (;;) {
        if (threadIdx.x == 0) task_s = atomicAdd(&g_ctr0, 1u);
        __syncthreads();
        unsigned task = task_s;
        if (task >= 512u) break;
        int bb = task >> 4, m0 = ((task >> 2) & 3) * 128, n0 = (task & 3) * 128;
        gemm_tile<0>(a, bm, out, bb, m0, n0);
        __syncthreads();
    }
}

__global__ __launch_bounds__(NT, 2)
void k_gemm12p(const float* __restrict__ a, const float* __restrict__ bm,
               float* __restrict__ out) {
    __shared__ unsigned task_s;
    for (;;) {
        if (threadIdx.x == 0) task_s = atomicAdd(&g_ctr12, 1u);
        __syncthreads();
        unsigned task = task_s;
        if (task >= 1024u) break;
        unsigned sub = task & 511u;
        int bb = sub >> 4, m0 = ((sub >> 2) & 3) * 128, n0 = (sub & 3) * 128;
        if (task < 512u) gemm_tile<1>(a, bm, out, bb, m0, n0);
        else             gemm_tile<2>(a, bm, out, bb, m0, n0);
        __syncthreads();
    }
}

// ---------------------------------------------------------------------------

extern "C" void kernel_launch(void* const* d_in, const int* in_sizes, int n_in,
                              void* d_out, int out_size) {
    const float* a  = (const float*)d_in[0];
    const float* bm = (const float*)d_in[1];
    float* out = (float*)d_out;
    (void)in_sizes; (void)n_in; (void)out_size;

    const int SMEM0 = 2 * STAGE0;                     // 81920 (2 CTAs/SM)
    int smem12 = 4 * STAGE12;                         // 75776
    if (smem12 < 128 * PFS * 4) smem12 = 128 * PFS * 4;

    static int configured = 0;
    if (!configured) {
        cudaFuncSetAttribute(k_gemm0p,  cudaFuncAttributeMaxDynamicSharedMemorySize, SMEM0);
        cudaFuncSetAttribute(k_gemm12p, cudaFuncAttributeMaxDynamicSharedMemorySize, smem12);
        configured = 1;
    }

    k_split<<<dim3(8192, 2), 256>>>(a, bm);
    k_gemm0p<<<2 * PGRID, NT, SMEM0>>>(a, bm, out);
    k_cstats<<<dim3(8, NB), 512>>>();
    k_pmat<<<dim3(S / 8, NB), 256>>>();
    k_gemm12p<<<2 * PGRID, NT, smem12>>>(a, bm, out);
}